// round 12
// baseline (speedup 1.0000x reference)
#include <cuda_runtime.h>
#include <cuda_bf16.h>
#include <math.h>
#include <stdint.h>

#define BATCH 8
#define CIN   64
#define COUT  128
#define EDIM  128
#define HIN   192
#define WIN   384
#define OH    96
#define OW    192
#define TOPK  32
#define OUT6_SIZE (BATCH*COUT*OH*OW)

typedef unsigned long long u64;
typedef unsigned int u32;

#define XTROWS 193
#define XTPX   385
#define O2R 98
#define O2PX 194

__device__ __nv_bfloat16 d_xt[(size_t)BATCH*XTROWS*XTPX*64];
__device__ __nv_bfloat16 d_o2[(size_t)BATCH*O2R*O2PX*32];
__device__ __nv_bfloat16 d_w1p[BATCH*576*32];
__device__ __nv_bfloat16 d_w2p[BATCH*288*32];
__device__ float d_dswt[CIN*COUT];           // dsw transposed [ci][co]
__device__ int   d_idx1[BATCH*TOPK];
__device__ float d_gv1 [BATCH*TOPK];
__device__ int   d_idx2[BATCH*TOPK];
__device__ float d_gv2 [BATCH*TOPK];
__device__ int   d_slot2[BATCH*COUT];

__device__ __forceinline__ float leaky(float v) { return v >= 0.f ? v : 0.2f * v; }
__device__ __forceinline__ u64 pk2(float lo, float hi) {
    u64 r; asm("mov.b64 %0, {%1, %2};" : "=l"(r) : "f"(lo), "f"(hi)); return r;
}
__device__ __forceinline__ void upk2(u64 v, float& lo, float& hi) {
    asm("mov.b64 {%0, %1}, %2;" : "=f"(lo), "=f"(hi) : "l"(v));
}
__device__ __forceinline__ void fma2(u64& d, u64 a, u64 b) {
    asm("fma.rn.f32x2 %0, %1, %2, %0;" : "+l"(d) : "l"(a), "l"(b));
}
__device__ __forceinline__ unsigned smem_u32(const void* p) {
    return (unsigned)__cvta_generic_to_shared(p);
}
__device__ __forceinline__ void cp4(unsigned dst, const void* src, int sz) {
    asm volatile("cp.async.ca.shared.global [%0], [%1], 4, %2;" :: "r"(dst), "l"(src), "r"(sz));
}
__device__ __forceinline__ void cp16(unsigned dst, const void* src) {
    asm volatile("cp.async.ca.shared.global [%0], [%1], 16;" :: "r"(dst), "l"(src));
}
#define CP_COMMIT() asm volatile("cp.async.commit_group;")
#define CP_WAIT0()  asm volatile("cp.async.wait_group 0;")

__device__ __forceinline__ void ldsm_x4(u32* r, unsigned a) {
    asm volatile("ldmatrix.sync.aligned.m8n8.x4.shared.b16 {%0,%1,%2,%3}, [%4];"
        : "=r"(r[0]), "=r"(r[1]), "=r"(r[2]), "=r"(r[3]) : "r"(a));
}
__device__ __forceinline__ void ldsm_x2t(u32* r, unsigned a) {
    asm volatile("ldmatrix.sync.aligned.m8n8.x2.trans.shared.b16 {%0,%1}, [%2];"
        : "=r"(r[0]), "=r"(r[1]) : "r"(a));
}
__device__ __forceinline__ void mma_bf16(float* d, const u32* a, const u32* b) {
    asm volatile("mma.sync.aligned.m16n8k16.row.col.f32.bf16.bf16.f32 "
        "{%0,%1,%2,%3}, {%4,%5,%6,%7}, {%8,%9}, {%0,%1,%2,%3};"
        : "+f"(d[0]), "+f"(d[1]), "+f"(d[2]), "+f"(d[3])
        : "r"(a[0]), "r"(a[1]), "r"(a[2]), "r"(a[3]), "r"(b[0]), "r"(b[1]));
}

// ============================================================================
// xt: x NCHW f32 -> d_xt NHWC bf16 (zero halos untouched). grid (6,192,8), 256.
// ============================================================================
__global__ void __launch_bounds__(256) xt_kernel(const float* __restrict__ x) {
    const int wc = blockIdx.x, r = blockIdx.y, b = blockIdx.z;
    const int w0 = wc * 64;
    const int tid = threadIdx.x;
    __shared__ float s[64][65];
    #pragma unroll 4
    for (int i = tid; i < 4096; i += 256) {
        int ci = i >> 6, w = i & 63;
        s[ci][w] = x[((size_t)(b * 64 + ci) * HIN + r) * WIN + w0 + w];
    }
    __syncthreads();
    const int px = tid >> 2, q = tid & 3;
    u32 pk[8];
    #pragma unroll
    for (int j = 0; j < 8; j++) {
        __nv_bfloat162 t = __floats2bfloat162_rn(s[q * 16 + 2 * j][px], s[q * 16 + 2 * j + 1][px]);
        pk[j] = *(u32*)&t;
    }
    uint4* dst = (uint4*)(d_xt + (((size_t)(b * XTROWS + r + 1) * XTPX + w0 + px + 1) * 64 + q * 16));
    dst[0] = make_uint4(pk[0], pk[1], pk[2], pk[3]);
    dst[1] = make_uint4(pk[4], pk[5], pk[6], pk[7]);
}

// ============================================================================
// Gate (unchanged)
// ============================================================================
__global__ void gate_kernel(const float* __restrict__ emb,
                            const float* __restrict__ g1w, const float* __restrict__ g1b,
                            const float* __restrict__ g2w, const float* __restrict__ g2b,
                            float* __restrict__ out) {
    const int b = blockIdx.x, gate = blockIdx.y, c = threadIdx.x;
    const float* gw = (gate == 0) ? g1w : g2w;
    const float* gb = (gate == 0) ? g1b : g2b;
    __shared__ float s_emb[EDIM];
    __shared__ float s_log[COUT];
    __shared__ float s_exp[COUT];
    s_emb[c] = emb[b * EDIM + c];
    __syncthreads();
    float l = gb[c];
    #pragma unroll 8
    for (int e = 0; e < EDIM; e++) l += s_emb[e] * gw[e * COUT + c];
    s_log[c] = l;
    __syncthreads();
    int rank = 0; float m = -1e30f;
    for (int j = 0; j < COUT; j++) {
        float lj = s_log[j];
        if (lj > l || (lj == l && j < c)) rank++;
        if (lj > m) m = lj;
    }
    bool sel = (rank < TOPK);
    float ev = sel ? expf(l - m) : 0.0f;
    s_exp[c] = ev;
    __syncthreads();
    float s = 0.f;
    for (int j = 0; j < COUT; j++) s += s_exp[j];
    float gv = ev / s;
    out[OUT6_SIZE + gate * (BATCH * COUT) + b * COUT + c] = gv;
    if (gate == 0) {
        if (sel) { d_idx1[b * TOPK + rank] = c; d_gv1[b * TOPK + rank] = gv; }
    } else {
        d_slot2[b * COUT + c] = sel ? rank : -1;
        if (sel) { d_idx2[b * TOPK + rank] = c; d_gv2[b * TOPK + rank] = gv; }
    }
}

// ============================================================================
// wpack: b<8 gather+scale conv weights; b==8 transpose dsw -> d_dswt. grid 9.
// ============================================================================
__global__ void __launch_bounds__(256) wpack_kernel(const float* __restrict__ w1,
                                                    const float* __restrict__ w2,
                                                    const float* __restrict__ dsw) {
    const int b = blockIdx.x, tid = threadIdx.x;
    if (b == 8) {
        for (int i = tid; i < CIN * COUT; i += 256) {
            int ci = i >> 7, co = i & 127;
            d_dswt[i] = dsw[co * CIN + ci];
        }
        return;
    }
    for (int i = tid; i < 32 * 576; i += 256) {
        int co = i / 576, kk = i - co * 576;
        int ci = kk / 9, tap = kk - ci * 9;
        float v = w1[((size_t)d_idx1[b * 32 + co] * 64 + ci) * 9 + tap] * d_gv1[b * 32 + co];
        d_w1p[(size_t)b * 18432 + (tap * 64 + ci) * 32 + co] = __float2bfloat16(v);
    }
    for (int i = tid; i < 32 * 288; i += 256) {
        int co = i / 288, kk = i - co * 288;
        int ci = kk / 9, tap = kk - ci * 9;
        float v = w2[((size_t)d_idx2[b * 32 + co] * 128 + d_idx1[b * 32 + ci]) * 9 + tap] * d_gv2[b * 32 + co];
        d_w2p[(size_t)b * 9216 + (tap * 32 + ci) * 32 + co] = __float2bfloat16(v);
    }
}

// ============================================================================
// ds: fp32, all 128 co/block; weights from pre-transposed d_dswt via cp16.
// ============================================================================
#define DS_SMEM ((8192 + 8192 + 384) * 4)
__global__ void __launch_bounds__(256, 2) ds_kernel(const float* __restrict__ x,
                                                    const float* __restrict__ gamma,
                                                    const float* __restrict__ beta,
                                                    float* __restrict__ out) {
    extern __shared__ __align__(16) float dsm[];
    float* s_xc    = dsm;
    float* s_wt    = dsm + 8192;
    float* s_scale = dsm + 16384;
    float* s_betav = s_scale + 128;
    int*   s_slot  = (int*)(s_betav + 128);

    const int b  = blockIdx.y;
    const int h0 = (blockIdx.x / 12) * 8;
    const int w0 = (blockIdx.x % 12) * 16;
    const int tid = threadIdx.x;
    const int po  = tid >> 4;
    const int cg  = tid & 15;

    const float* xb = x + (size_t)b * CIN * HIN * WIN;
    #pragma unroll 8
    for (int k = 0; k < 32; k++) {
        int i = tid + k * 256;
        int ci = i >> 7, p = i & 127, r = (p >> 4), j = p & 15;
        cp4(smem_u32(&s_xc[i]), xb + (size_t)ci * HIN * WIN + (2 * (h0 + r)) * WIN + 2 * (w0 + j), 4);
    }
    #pragma unroll
    for (int k = 0; k < 8; k++) {
        int i = tid + k * 256;                         // 2048 x 16B chunks
        cp16(smem_u32(&s_wt[i * 4]), d_dswt + i * 4);
    }
    if (tid < 128) {
        s_scale[tid] = gamma[tid] * rsqrtf(1.0f + 1e-5f);
        s_betav[tid] = beta[tid];
        s_slot[tid]  = d_slot2[b * COUT + tid];
    }
    CP_COMMIT(); CP_WAIT0();
    __syncthreads();

    u64 acc[8][4];
    #pragma unroll
    for (int c = 0; c < 8; c++)
        #pragma unroll
        for (int m = 0; m < 4; m++) acc[c][m] = 0ull;

    #pragma unroll 4
    for (int ci = 0; ci < 64; ci++) {
        const ulonglong2* xq = (const ulonglong2*)&s_xc[ci * 128 + 8 * po];
        ulonglong2 X0 = xq[0], X1 = xq[1];
        const float4* wq = (const float4*)&s_wt[ci * 128 + 8 * cg];
        float4 wa = wq[0], wb2 = wq[1];
        u64 W[8];
        W[0] = pk2(wa.x, wa.x);   W[1] = pk2(wa.y, wa.y);
        W[2] = pk2(wa.z, wa.z);   W[3] = pk2(wa.w, wa.w);
        W[4] = pk2(wb2.x, wb2.x); W[5] = pk2(wb2.y, wb2.y);
        W[6] = pk2(wb2.z, wb2.z); W[7] = pk2(wb2.w, wb2.w);
        #pragma unroll
        for (int c = 0; c < 8; c++) {
            fma2(acc[c][0], X0.x, W[c]);
            fma2(acc[c][1], X0.y, W[c]);
            fma2(acc[c][2], X1.x, W[c]);
            fma2(acc[c][3], X1.y, W[c]);
        }
    }

    const int hr  = h0 + (po >> 1);
    const int wc0 = w0 + (po & 1) * 8;
    #pragma unroll
    for (int c = 0; c < 8; c++) {
        int co = 8 * cg + c;
        float v[8];
        #pragma unroll
        for (int m = 0; m < 4; m++) upk2(acc[c][m], v[2 * m], v[2 * m + 1]);
        float sc = s_scale[co], be = s_betav[co];
        #pragma unroll
        for (int k = 0; k < 8; k++) v[k] = v[k] * sc + be;
        if (s_slot[co] < 0) {
            #pragma unroll
            for (int k = 0; k < 8; k++) v[k] = leaky(v[k]);
        }
        float* base = &out[((size_t)(b * COUT + co) * OH + hr) * OW + wc0];
        *(float4*)base       = make_float4(v[0], v[1], v[2], v[3]);
        *(float4*)(base + 4) = make_float4(v[4], v[5], v[6], v[7]);
    }
}

// ============================================================================
// conv1_tc: mma.sync bf16, 4 output rows per block (weights staged once).
// grid (2, 24, BATCH), 192 thr. sep epilogue region overlaps sx only.
// ============================================================================
#define C1_ROWB (XTPX * 128)
#define C1_SMEM (3 * 193 * 128 + 18432 * 2)
__global__ void __launch_bounds__(192, 2) conv1_tc() {
    extern __shared__ __align__(16) char sm1[];
    char* sx = sm1;
    char* sw = sm1 + 3 * 193 * 128;
    float* sep = (float*)sm1;

    const int half = blockIdx.x, hq = blockIdx.y, b = blockIdx.z;
    const int w0 = half * 96;
    const int tid = threadIdx.x, wid = tid >> 5, lane = tid & 31;

    {
        const char* wb = (const char*)(d_w1p + (size_t)b * 18432);
        for (int i = tid; i < 2304; i += 192)
            cp16(smem_u32(sw + i * 16), wb + i * 16);
        CP_COMMIT();
    }

    const int moff = lane & 15;
    const int kbyte = (lane < 16) ? 0 : 16;
    const int mpx = wid * 16 + moff;
    const unsigned sxb = smem_u32(sx);
    const unsigned swb = smem_u32(sw);
    const int brow0 = (lane & 15) * 64;

    for (int r4 = 0; r4 < 4; r4++) {
        const int h = hq * 4 + r4;
        __syncthreads();                              // prev epilogue done with sep
        {
            const char* xb = (const char*)(d_xt + (((size_t)(b * XTROWS + 2 * h) * XTPX + 2 * w0) * 64));
            for (int i = tid; i < 3 * 1544; i += 192) {
                int r = i / 1544, off = (i - r * 1544) * 16;
                cp16(smem_u32(sx + r * (193 * 128) + off), xb + (size_t)r * C1_ROWB + off);
            }
            CP_COMMIT(); CP_WAIT0();
        }
        __syncthreads();

        float acc[4][4];
        #pragma unroll
        for (int n = 0; n < 4; n++)
            #pragma unroll
            for (int k = 0; k < 4; k++) acc[n][k] = 0.f;

        #pragma unroll 4
        for (int kc = 0; kc < 36; kc++) {
            const int tap = kc >> 2, cc = kc & 3;
            const int dh = tap / 3, dw = tap - 3 * dh;
            u32 a[4];
            ldsm_x4(a, sxb + dh * (193 * 128) + (2 * mpx + dw) * 128 + cc * 32 + kbyte);
            const unsigned bbase = swb + kc * 16 * 64 + brow0;
            #pragma unroll
            for (int n = 0; n < 4; n++) {
                u32 bb[2];
                ldsm_x2t(bb, bbase + n * 16);
                mma_bf16(acc[n], a, bb);
            }
        }
        __syncthreads();

        const int gid = lane >> 2, tig = lane & 3;
        #pragma unroll
        for (int n = 0; n < 4; n++) {
            int co = n * 8 + 2 * tig;
            int p0 = wid * 16 + gid;
            sep[p0 * 33 + co]           = acc[n][0];
            sep[p0 * 33 + co + 1]       = acc[n][1];
            sep[(p0 + 8) * 33 + co]     = acc[n][2];
            sep[(p0 + 8) * 33 + co + 1] = acc[n][3];
        }
        __syncthreads();

        const int px = tid >> 1, hc = tid & 1;
        u32 pk[8];
        #pragma unroll
        for (int j = 0; j < 8; j++) {
            float v0 = leaky(sep[px * 33 + hc * 16 + 2 * j]);
            float v1 = leaky(sep[px * 33 + hc * 16 + 2 * j + 1]);
            __nv_bfloat162 t = __floats2bfloat162_rn(v0, v1);
            pk[j] = *(u32*)&t;
        }
        uint4* dst = (uint4*)(d_o2 + (((size_t)(b * O2R + h + 1) * O2PX + 1 + w0 + px) * 32 + hc * 16));
        dst[0] = make_uint4(pk[0], pk[1], pk[2], pk[3]);
        dst[1] = make_uint4(pk[4], pk[5], pk[6], pk[7]);
    }
}

// ============================================================================
// conv2_tc: mma.sync bf16, 4 rows per block (weights staged once), fused
// epilogue leaky(leaky(v)+ident). grid (24, BATCH), 192 thr.
// ============================================================================
#define C2_ROWB (O2PX * 64)
#define C2_SMEM (3 * C2_ROWB + 9216 * 2)
__global__ void __launch_bounds__(192, 3) conv2_tc(float* __restrict__ out) {
    extern __shared__ __align__(16) char sm2[];
    char* sx = sm2;
    char* sw = sm2 + 3 * C2_ROWB;
    float* sep = (float*)sm2;
    __shared__ int s_idx2s[32];

    const int hq = blockIdx.x, b = blockIdx.y;
    const int tid = threadIdx.x, wid = tid >> 5, lane = tid & 31;

    {
        const char* wb = (const char*)(d_w2p + (size_t)b * 9216);
        for (int i = tid; i < 1152; i += 192)
            cp16(smem_u32(sw + i * 16), wb + i * 16);
        if (tid < 32) s_idx2s[tid] = d_idx2[b * 32 + tid];
        CP_COMMIT();
    }

    const int moff = lane & 15;
    const int kbyte = (lane < 16) ? 0 : 16;
    const unsigned sxb = smem_u32(sx);
    const unsigned swb = smem_u32(sw);
    const int brow0 = (lane & 15) * 64;

    for (int r4 = 0; r4 < 4; r4++) {
        const int h = hq * 4 + r4;
        __syncthreads();
        {
            const char* xb = (const char*)(d_o2 + ((size_t)(b * O2R + h) * O2PX) * 32);
            for (int i = tid; i < 3 * 776; i += 192) {
                int r = i / 776, off = (i - r * 776) * 16;
                cp16(smem_u32(sx + r * C2_ROWB + off), xb + (size_t)r * C2_ROWB + off);
            }
            CP_COMMIT(); CP_WAIT0();
        }
        __syncthreads();

        float acc[2][4][4];
        #pragma unroll
        for (int mi = 0; mi < 2; mi++)
            #pragma unroll
            for (int n = 0; n < 4; n++)
                #pragma unroll
                for (int k = 0; k < 4; k++) acc[mi][n][k] = 0.f;

        #pragma unroll 3
        for (int kc = 0; kc < 18; kc++) {
            const int tap = kc >> 1, cc = kc & 1;
            const int dh = tap / 3, dw = tap - 3 * dh;
            u32 bb[4][2];
            const unsigned bbase = swb + kc * 16 * 64 + brow0;
            #pragma unroll
            for (int n = 0; n < 4; n++) ldsm_x2t(bb[n], bbase + n * 16);
            #pragma unroll
            for (int mi = 0; mi < 2; mi++) {
                u32 a[4];
                const int p = (2 * wid + mi) * 16 + moff + dw;
                ldsm_x4(a, sxb + dh * C2_ROWB + p * 64 + cc * 32 + kbyte);
                #pragma unroll
                for (int n = 0; n < 4; n++) mma_bf16(acc[mi][n], a, bb[n]);
            }
        }
        __syncthreads();

        const int gid = lane >> 2, tig = lane & 3;
        #pragma unroll
        for (int mi = 0; mi < 2; mi++) {
            int p0 = (2 * wid + mi) * 16 + gid;
            #pragma unroll
            for (int n = 0; n < 4; n++) {
                int co = n * 8 + 2 * tig;
                sep[p0 * 33 + co]           = acc[mi][n][0];
                sep[p0 * 33 + co + 1]       = acc[mi][n][1];
                sep[(p0 + 8) * 33 + co]     = acc[mi][n][2];
                sep[(p0 + 8) * 33 + co + 1] = acc[mi][n][3];
            }
        }
        __syncthreads();

        for (int co = 0; co < 32; co++) {
            float v = sep[tid * 33 + co];
            float* op = &out[((size_t)(b * COUT + s_idx2s[co]) * OH + h) * OW + tid];
            *op = leaky(leaky(v) + *op);
        }
    }
}

// ============================================================================
extern "C" void kernel_launch(void* const* d_in, const int* in_sizes, int n_in,
                              void* d_out, int out_size) {
    const float* x     = (const float*)d_in[0];
    const float* emb   = (const float*)d_in[1];
    const float* w1    = (const float*)d_in[2];
    const float* w2    = (const float*)d_in[3];
    const float* dsw   = (const float*)d_in[4];
    const float* gam   = (const float*)d_in[5];
    const float* bet   = (const float*)d_in[6];
    const float* g1w   = (const float*)d_in[7];
    const float* g1b   = (const float*)d_in[8];
    const float* g2w   = (const float*)d_in[9];
    const float* g2b   = (const float*)d_in[10];
    float* out = (float*)d_out;

    cudaFuncSetAttribute(ds_kernel, cudaFuncAttributeMaxDynamicSharedMemorySize, DS_SMEM);
    cudaFuncSetAttribute(conv1_tc,  cudaFuncAttributeMaxDynamicSharedMemorySize, C1_SMEM);
    cudaFuncSetAttribute(conv2_tc,  cudaFuncAttributeMaxDynamicSharedMemorySize, C2_SMEM);

    gate_kernel<<<dim3(BATCH, 2), 128>>>(emb, g1w, g1b, g2w, g2b, out);
    xt_kernel<<<dim3(6, 192, BATCH), 256>>>(x);
    wpack_kernel<<<9, 256>>>(w1, w2, dsw);
    ds_kernel<<<dim3(144, BATCH), 256, DS_SMEM>>>(x, gam, bet, out);
    conv1_tc<<<dim3(2, 24, BATCH), 192, C1_SMEM>>>();
    conv2_tc<<<dim3(24, BATCH), 192, C2_SMEM>>>(out);
}

// round 13
// speedup vs baseline: 1.1410x; 1.1410x over previous
#include <cuda_runtime.h>
#include <cuda_bf16.h>
#include <math.h>
#include <stdint.h>

#define BATCH 8
#define CIN   64
#define COUT  128
#define EDIM  128
#define HIN   192
#define WIN   384
#define OH    96
#define OW    192
#define TOPK  32
#define OUT6_SIZE (BATCH*COUT*OH*OW)

typedef unsigned long long u64;
typedef unsigned int u32;

#define XTROWS 193
#define XTPX   385
#define O2R 98
#define O2PX 194

__device__ __nv_bfloat16 d_xt[(size_t)BATCH*XTROWS*XTPX*64];
__device__ __nv_bfloat16 d_o2[(size_t)BATCH*O2R*O2PX*32];
__device__ __nv_bfloat16 d_w1p[BATCH*576*32];
__device__ __nv_bfloat16 d_w2p[BATCH*288*32];
__device__ float d_dswt[CIN*COUT];           // dsw transposed [ci][co]
__device__ int   d_idx1[BATCH*TOPK];
__device__ float d_gv1 [BATCH*TOPK];
__device__ int   d_idx2[BATCH*TOPK];
__device__ float d_gv2 [BATCH*TOPK];
__device__ int   d_slot2[BATCH*COUT];

__device__ __forceinline__ float leaky(float v) { return v >= 0.f ? v : 0.2f * v; }
__device__ __forceinline__ u64 pk2(float lo, float hi) {
    u64 r; asm("mov.b64 %0, {%1, %2};" : "=l"(r) : "f"(lo), "f"(hi)); return r;
}
__device__ __forceinline__ void upk2(u64 v, float& lo, float& hi) {
    asm("mov.b64 {%0, %1}, %2;" : "=f"(lo), "=f"(hi) : "l"(v));
}
__device__ __forceinline__ void fma2(u64& d, u64 a, u64 b) {
    asm("fma.rn.f32x2 %0, %1, %2, %0;" : "+l"(d) : "l"(a), "l"(b));
}
__device__ __forceinline__ unsigned smem_u32(const void* p) {
    return (unsigned)__cvta_generic_to_shared(p);
}
__device__ __forceinline__ void cp4(unsigned dst, const void* src, int sz) {
    asm volatile("cp.async.ca.shared.global [%0], [%1], 4, %2;" :: "r"(dst), "l"(src), "r"(sz));
}
__device__ __forceinline__ void cp16(unsigned dst, const void* src) {
    asm volatile("cp.async.ca.shared.global [%0], [%1], 16;" :: "r"(dst), "l"(src));
}
#define CP_COMMIT() asm volatile("cp.async.commit_group;")
#define CP_WAIT0()  asm volatile("cp.async.wait_group 0;")

__device__ __forceinline__ void ldsm_x4(u32* r, unsigned a) {
    asm volatile("ldmatrix.sync.aligned.m8n8.x4.shared.b16 {%0,%1,%2,%3}, [%4];"
        : "=r"(r[0]), "=r"(r[1]), "=r"(r[2]), "=r"(r[3]) : "r"(a));
}
__device__ __forceinline__ void ldsm_x2t(u32* r, unsigned a) {
    asm volatile("ldmatrix.sync.aligned.m8n8.x2.trans.shared.b16 {%0,%1}, [%2];"
        : "=r"(r[0]), "=r"(r[1]) : "r"(a));
}
__device__ __forceinline__ void mma_bf16(float* d, const u32* a, const u32* b) {
    asm volatile("mma.sync.aligned.m16n8k16.row.col.f32.bf16.bf16.f32 "
        "{%0,%1,%2,%3}, {%4,%5,%6,%7}, {%8,%9}, {%0,%1,%2,%3};"
        : "+f"(d[0]), "+f"(d[1]), "+f"(d[2]), "+f"(d[3])
        : "r"(a[0]), "r"(a[1]), "r"(a[2]), "r"(a[3]), "r"(b[0]), "r"(b[1]));
}

// ============================================================================
// xt: x NCHW f32 -> d_xt NHWC bf16 (zero halos untouched). grid (6,192,8), 256.
// ============================================================================
__global__ void __launch_bounds__(256) xt_kernel(const float* __restrict__ x) {
    const int wc = blockIdx.x, r = blockIdx.y, b = blockIdx.z;
    const int w0 = wc * 64;
    const int tid = threadIdx.x;
    __shared__ float s[64][65];
    #pragma unroll 4
    for (int i = tid; i < 4096; i += 256) {
        int ci = i >> 6, w = i & 63;
        s[ci][w] = x[((size_t)(b * 64 + ci) * HIN + r) * WIN + w0 + w];
    }
    __syncthreads();
    const int px = tid >> 2, q = tid & 3;
    u32 pk[8];
    #pragma unroll
    for (int j = 0; j < 8; j++) {
        __nv_bfloat162 t = __floats2bfloat162_rn(s[q * 16 + 2 * j][px], s[q * 16 + 2 * j + 1][px]);
        pk[j] = *(u32*)&t;
    }
    uint4* dst = (uint4*)(d_xt + (((size_t)(b * XTROWS + r + 1) * XTPX + w0 + px + 1) * 64 + q * 16));
    dst[0] = make_uint4(pk[0], pk[1], pk[2], pk[3]);
    dst[1] = make_uint4(pk[4], pk[5], pk[6], pk[7]);
}

// ============================================================================
// Gate (unchanged)
// ============================================================================
__global__ void gate_kernel(const float* __restrict__ emb,
                            const float* __restrict__ g1w, const float* __restrict__ g1b,
                            const float* __restrict__ g2w, const float* __restrict__ g2b,
                            float* __restrict__ out) {
    const int b = blockIdx.x, gate = blockIdx.y, c = threadIdx.x;
    const float* gw = (gate == 0) ? g1w : g2w;
    const float* gb = (gate == 0) ? g1b : g2b;
    __shared__ float s_emb[EDIM];
    __shared__ float s_log[COUT];
    __shared__ float s_exp[COUT];
    s_emb[c] = emb[b * EDIM + c];
    __syncthreads();
    float l = gb[c];
    #pragma unroll 8
    for (int e = 0; e < EDIM; e++) l += s_emb[e] * gw[e * COUT + c];
    s_log[c] = l;
    __syncthreads();
    int rank = 0; float m = -1e30f;
    for (int j = 0; j < COUT; j++) {
        float lj = s_log[j];
        if (lj > l || (lj == l && j < c)) rank++;
        if (lj > m) m = lj;
    }
    bool sel = (rank < TOPK);
    float ev = sel ? expf(l - m) : 0.0f;
    s_exp[c] = ev;
    __syncthreads();
    float s = 0.f;
    for (int j = 0; j < COUT; j++) s += s_exp[j];
    float gv = ev / s;
    out[OUT6_SIZE + gate * (BATCH * COUT) + b * COUT + c] = gv;
    if (gate == 0) {
        if (sel) { d_idx1[b * TOPK + rank] = c; d_gv1[b * TOPK + rank] = gv; }
    } else {
        d_slot2[b * COUT + c] = sel ? rank : -1;
        if (sel) { d_idx2[b * TOPK + rank] = c; d_gv2[b * TOPK + rank] = gv; }
    }
}

// ============================================================================
// wpack: b<8 gather+scale conv weights; b==8 transpose dsw -> d_dswt. grid 9.
// ============================================================================
__global__ void __launch_bounds__(256) wpack_kernel(const float* __restrict__ w1,
                                                    const float* __restrict__ w2,
                                                    const float* __restrict__ dsw) {
    const int b = blockIdx.x, tid = threadIdx.x;
    if (b == 8) {
        for (int i = tid; i < CIN * COUT; i += 256) {
            int ci = i >> 7, co = i & 127;
            d_dswt[i] = dsw[co * CIN + ci];
        }
        return;
    }
    for (int i = tid; i < 32 * 576; i += 256) {
        int co = i / 576, kk = i - co * 576;
        int ci = kk / 9, tap = kk - ci * 9;
        float v = w1[((size_t)d_idx1[b * 32 + co] * 64 + ci) * 9 + tap] * d_gv1[b * 32 + co];
        d_w1p[(size_t)b * 18432 + (tap * 64 + ci) * 32 + co] = __float2bfloat16(v);
    }
    for (int i = tid; i < 32 * 288; i += 256) {
        int co = i / 288, kk = i - co * 288;
        int ci = kk / 9, tap = kk - ci * 9;
        float v = w2[((size_t)d_idx2[b * 32 + co] * 128 + d_idx1[b * 32 + ci]) * 9 + tap] * d_gv2[b * 32 + co];
        d_w2p[(size_t)b * 9216 + (tap * 32 + ci) * 32 + co] = __float2bfloat16(v);
    }
}

// ============================================================================
// ds (R12 version — the 72 µs one): weights from pre-transposed d_dswt.
// ============================================================================
#define DS_SMEM ((8192 + 8192 + 384) * 4)
__global__ void __launch_bounds__(256, 2) ds_kernel(const float* __restrict__ x,
                                                    const float* __restrict__ gamma,
                                                    const float* __restrict__ beta,
                                                    float* __restrict__ out) {
    extern __shared__ __align__(16) float dsm[];
    float* s_xc    = dsm;
    float* s_wt    = dsm + 8192;
    float* s_scale = dsm + 16384;
    float* s_betav = s_scale + 128;
    int*   s_slot  = (int*)(s_betav + 128);

    const int b  = blockIdx.y;
    const int h0 = (blockIdx.x / 12) * 8;
    const int w0 = (blockIdx.x % 12) * 16;
    const int tid = threadIdx.x;
    const int po  = tid >> 4;
    const int cg  = tid & 15;

    const float* xb = x + (size_t)b * CIN * HIN * WIN;
    #pragma unroll 8
    for (int k = 0; k < 32; k++) {
        int i = tid + k * 256;
        int ci = i >> 7, p = i & 127, r = (p >> 4), j = p & 15;
        cp4(smem_u32(&s_xc[i]), xb + (size_t)ci * HIN * WIN + (2 * (h0 + r)) * WIN + 2 * (w0 + j), 4);
    }
    #pragma unroll
    for (int k = 0; k < 8; k++) {
        int i = tid + k * 256;
        cp16(smem_u32(&s_wt[i * 4]), d_dswt + i * 4);
    }
    if (tid < 128) {
        s_scale[tid] = gamma[tid] * rsqrtf(1.0f + 1e-5f);
        s_betav[tid] = beta[tid];
        s_slot[tid]  = d_slot2[b * COUT + tid];
    }
    CP_COMMIT(); CP_WAIT0();
    __syncthreads();

    u64 acc[8][4];
    #pragma unroll
    for (int c = 0; c < 8; c++)
        #pragma unroll
        for (int m = 0; m < 4; m++) acc[c][m] = 0ull;

    #pragma unroll 4
    for (int ci = 0; ci < 64; ci++) {
        const ulonglong2* xq = (const ulonglong2*)&s_xc[ci * 128 + 8 * po];
        ulonglong2 X0 = xq[0], X1 = xq[1];
        const float4* wq = (const float4*)&s_wt[ci * 128 + 8 * cg];
        float4 wa = wq[0], wb2 = wq[1];
        u64 W[8];
        W[0] = pk2(wa.x, wa.x);   W[1] = pk2(wa.y, wa.y);
        W[2] = pk2(wa.z, wa.z);   W[3] = pk2(wa.w, wa.w);
        W[4] = pk2(wb2.x, wb2.x); W[5] = pk2(wb2.y, wb2.y);
        W[6] = pk2(wb2.z, wb2.z); W[7] = pk2(wb2.w, wb2.w);
        #pragma unroll
        for (int c = 0; c < 8; c++) {
            fma2(acc[c][0], X0.x, W[c]);
            fma2(acc[c][1], X0.y, W[c]);
            fma2(acc[c][2], X1.x, W[c]);
            fma2(acc[c][3], X1.y, W[c]);
        }
    }

    const int hr  = h0 + (po >> 1);
    const int wc0 = w0 + (po & 1) * 8;
    #pragma unroll
    for (int c = 0; c < 8; c++) {
        int co = 8 * cg + c;
        float v[8];
        #pragma unroll
        for (int m = 0; m < 4; m++) upk2(acc[c][m], v[2 * m], v[2 * m + 1]);
        float sc = s_scale[co], be = s_betav[co];
        #pragma unroll
        for (int k = 0; k < 8; k++) v[k] = v[k] * sc + be;
        if (s_slot[co] < 0) {
            #pragma unroll
            for (int k = 0; k < 8; k++) v[k] = leaky(v[k]);
        }
        float* base = &out[((size_t)(b * COUT + co) * OH + hr) * OW + wc0];
        *(float4*)base       = make_float4(v[0], v[1], v[2], v[3]);
        *(float4*)(base + 4) = make_float4(v[4], v[5], v[6], v[7]);
    }
}

// ============================================================================
// conv1_tc (R11 version — 1 row per block): grid (2, 96, BATCH), 192 thr.
// ============================================================================
#define C1_ROWB (XTPX * 128)
#define C1_SMEM (3 * 193 * 128 + 18432 * 2)
__global__ void __launch_bounds__(192, 2) conv1_tc() {
    extern __shared__ __align__(16) char sm1[];
    char* sx = sm1;
    char* sw = sm1 + 3 * 193 * 128;
    float* sep = (float*)sm1;

    const int half = blockIdx.x, h = blockIdx.y, b = blockIdx.z;
    const int w0 = half * 96;
    const int tid = threadIdx.x, wid = tid >> 5, lane = tid & 31;

    {
        const char* xb = (const char*)(d_xt + (((size_t)(b * XTROWS + 2 * h) * XTPX + 2 * w0) * 64));
        for (int i = tid; i < 3 * 1544; i += 192) {
            int r = i / 1544, off = (i - r * 1544) * 16;
            cp16(smem_u32(sx + r * (193 * 128) + off), xb + (size_t)r * C1_ROWB + off);
        }
        const char* wb = (const char*)(d_w1p + (size_t)b * 18432);
        for (int i = tid; i < 2304; i += 192)
            cp16(smem_u32(sw + i * 16), wb + i * 16);
        CP_COMMIT(); CP_WAIT0();
    }
    __syncthreads();

    float acc[4][4];
    #pragma unroll
    for (int n = 0; n < 4; n++)
        #pragma unroll
        for (int k = 0; k < 4; k++) acc[n][k] = 0.f;

    const int moff = lane & 15;
    const int kbyte = (lane < 16) ? 0 : 16;
    const int mpx = wid * 16 + moff;
    const unsigned sxb = smem_u32(sx);
    const unsigned swb = smem_u32(sw);
    const int brow0 = (lane & 15) * 64;

    #pragma unroll 4
    for (int kc = 0; kc < 36; kc++) {
        const int tap = kc >> 2, cc = kc & 3;
        const int dh = tap / 3, dw = tap - 3 * dh;
        u32 a[4];
        ldsm_x4(a, sxb + dh * (193 * 128) + (2 * mpx + dw) * 128 + cc * 32 + kbyte);
        const unsigned bbase = swb + kc * 16 * 64 + brow0;
        #pragma unroll
        for (int n = 0; n < 4; n++) {
            u32 bb[2];
            ldsm_x2t(bb, bbase + n * 16);
            mma_bf16(acc[n], a, bb);
        }
    }
    __syncthreads();

    const int gid = lane >> 2, tig = lane & 3;
    #pragma unroll
    for (int n = 0; n < 4; n++) {
        int co = n * 8 + 2 * tig;
        int p0 = wid * 16 + gid;
        sep[p0 * 33 + co]           = acc[n][0];
        sep[p0 * 33 + co + 1]       = acc[n][1];
        sep[(p0 + 8) * 33 + co]     = acc[n][2];
        sep[(p0 + 8) * 33 + co + 1] = acc[n][3];
    }
    __syncthreads();

    const int px = tid >> 1, hc = tid & 1;
    u32 pk[8];
    #pragma unroll
    for (int j = 0; j < 8; j++) {
        float v0 = leaky(sep[px * 33 + hc * 16 + 2 * j]);
        float v1 = leaky(sep[px * 33 + hc * 16 + 2 * j + 1]);
        __nv_bfloat162 t = __floats2bfloat162_rn(v0, v1);
        pk[j] = *(u32*)&t;
    }
    uint4* dst = (uint4*)(d_o2 + (((size_t)(b * O2R + h + 1) * O2PX + 1 + w0 + px) * 32 + hc * 16));
    dst[0] = make_uint4(pk[0], pk[1], pk[2], pk[3]);
    dst[1] = make_uint4(pk[4], pk[5], pk[6], pk[7]);
}

// ============================================================================
// conv2_tc (R11 version — 1 row per block): grid (96, BATCH), 192 thr.
// ============================================================================
#define C2_ROWB (O2PX * 64)
#define C2_SMEM (3 * C2_ROWB + 9216 * 2)
__global__ void __launch_bounds__(192, 3) conv2_tc(float* __restrict__ out) {
    extern __shared__ __align__(16) char sm2[];
    char* sx = sm2;
    char* sw = sm2 + 3 * C2_ROWB;
    float* sep = (float*)sm2;
    __shared__ int s_idx2s[32];

    const int h = blockIdx.x, b = blockIdx.y;
    const int tid = threadIdx.x, wid = tid >> 5, lane = tid & 31;

    {
        const char* xb = (const char*)(d_o2 + ((size_t)(b * O2R + h) * O2PX) * 32);
        for (int i = tid; i < 3 * 776; i += 192) {
            int r = i / 776, off = (i - r * 776) * 16;
            cp16(smem_u32(sx + r * C2_ROWB + off), xb + (size_t)r * C2_ROWB + off);
        }
        const char* wb = (const char*)(d_w2p + (size_t)b * 9216);
        for (int i = tid; i < 1152; i += 192)
            cp16(smem_u32(sw + i * 16), wb + i * 16);
        if (tid < 32) s_idx2s[tid] = d_idx2[b * 32 + tid];
        CP_COMMIT(); CP_WAIT0();
    }
    __syncthreads();

    float acc[2][4][4];
    #pragma unroll
    for (int mi = 0; mi < 2; mi++)
        #pragma unroll
        for (int n = 0; n < 4; n++)
            #pragma unroll
            for (int k = 0; k < 4; k++) acc[mi][n][k] = 0.f;

    const int moff = lane & 15;
    const int kbyte = (lane < 16) ? 0 : 16;
    const unsigned sxb = smem_u32(sx);
    const unsigned swb = smem_u32(sw);
    const int brow0 = (lane & 15) * 64;

    #pragma unroll 3
    for (int kc = 0; kc < 18; kc++) {
        const int tap = kc >> 1, cc = kc & 1;
        const int dh = tap / 3, dw = tap - 3 * dh;
        u32 bb[4][2];
        const unsigned bbase = swb + kc * 16 * 64 + brow0;
        #pragma unroll
        for (int n = 0; n < 4; n++) ldsm_x2t(bb[n], bbase + n * 16);
        #pragma unroll
        for (int mi = 0; mi < 2; mi++) {
            u32 a[4];
            const int p = (2 * wid + mi) * 16 + moff + dw;
            ldsm_x4(a, sxb + dh * C2_ROWB + p * 64 + cc * 32 + kbyte);
            #pragma unroll
            for (int n = 0; n < 4; n++) mma_bf16(acc[mi][n], a, bb[n]);
        }
    }
    __syncthreads();

    const int gid = lane >> 2, tig = lane & 3;
    #pragma unroll
    for (int mi = 0; mi < 2; mi++) {
        int p0 = (2 * wid + mi) * 16 + gid;
        #pragma unroll
        for (int n = 0; n < 4; n++) {
            int co = n * 8 + 2 * tig;
            sep[p0 * 33 + co]           = acc[mi][n][0];
            sep[p0 * 33 + co + 1]       = acc[mi][n][1];
            sep[(p0 + 8) * 33 + co]     = acc[mi][n][2];
            sep[(p0 + 8) * 33 + co + 1] = acc[mi][n][3];
        }
    }
    __syncthreads();

    for (int co = 0; co < 32; co++) {
        float v = sep[tid * 33 + co];
        float* op = &out[((size_t)(b * COUT + s_idx2s[co]) * OH + h) * OW + tid];
        *op = leaky(leaky(v) + *op);
    }
}

// ============================================================================
extern "C" void kernel_launch(void* const* d_in, const int* in_sizes, int n_in,
                              void* d_out, int out_size) {
    const float* x     = (const float*)d_in[0];
    const float* emb   = (const float*)d_in[1];
    const float* w1    = (const float*)d_in[2];
    const float* w2    = (const float*)d_in[3];
    const float* dsw   = (const float*)d_in[4];
    const float* gam   = (const float*)d_in[5];
    const float* bet   = (const float*)d_in[6];
    const float* g1w   = (const float*)d_in[7];
    const float* g1b   = (const float*)d_in[8];
    const float* g2w   = (const float*)d_in[9];
    const float* g2b   = (const float*)d_in[10];
    float* out = (float*)d_out;

    cudaFuncSetAttribute(ds_kernel, cudaFuncAttributeMaxDynamicSharedMemorySize, DS_SMEM);
    cudaFuncSetAttribute(conv1_tc,  cudaFuncAttributeMaxDynamicSharedMemorySize, C1_SMEM);
    cudaFuncSetAttribute(conv2_tc,  cudaFuncAttributeMaxDynamicSharedMemorySize, C2_SMEM);

    gate_kernel<<<dim3(BATCH, 2), 128>>>(emb, g1w, g1b, g2w, g2b, out);
    xt_kernel<<<dim3(6, 192, BATCH), 256>>>(x);
    wpack_kernel<<<9, 256>>>(w1, w2, dsw);
    ds_kernel<<<dim3(144, BATCH), 256, DS_SMEM>>>(x, gam, bet, out);
    conv1_tc<<<dim3(2, OH, BATCH), 192, C1_SMEM>>>();
    conv2_tc<<<dim3(OH, BATCH), 192, C2_SMEM>>>(out);
}

// round 16
// speedup vs baseline: 1.2198x; 1.0691x over previous
#include <cuda_runtime.h>
#include <cuda_bf16.h>
#include <math.h>
#include <stdint.h>

#define BATCH 8
#define CIN   64
#define COUT  128
#define EDIM  128
#define HIN   192
#define WIN   384
#define OH    96
#define OW    192
#define TOPK  32
#define OUT6_SIZE (BATCH*COUT*OH*OW)

typedef unsigned long long u64;
typedef unsigned int u32;

#define XTROWS 193
#define XTPX   385
#define O2R 98
#define O2PX 194

__device__ __nv_bfloat16 d_xt[(size_t)BATCH*XTROWS*XTPX*64];
__device__ __nv_bfloat16 d_o2[(size_t)BATCH*O2R*O2PX*32];
__device__ __nv_bfloat16 d_w1p[BATCH*576*32];
__device__ __nv_bfloat16 d_w2p[BATCH*288*32];
__device__ float d_dswt[CIN*COUT];           // dsw transposed [ci][co]
__device__ int   d_idx1[BATCH*TOPK];
__device__ float d_gv1 [BATCH*TOPK];
__device__ int   d_idx2[BATCH*TOPK];
__device__ float d_gv2 [BATCH*TOPK];
__device__ int   d_slot2[BATCH*COUT];

__device__ __forceinline__ float leaky(float v) { return v >= 0.f ? v : 0.2f * v; }
__device__ __forceinline__ u64 pk2(float lo, float hi) {
    u64 r; asm("mov.b64 %0, {%1, %2};" : "=l"(r) : "f"(lo), "f"(hi)); return r;
}
__device__ __forceinline__ void upk2(u64 v, float& lo, float& hi) {
    asm("mov.b64 {%0, %1}, %2;" : "=f"(lo), "=f"(hi) : "l"(v));
}
__device__ __forceinline__ void fma2(u64& d, u64 a, u64 b) {
    asm("fma.rn.f32x2 %0, %1, %2, %0;" : "+l"(d) : "l"(a), "l"(b));
}
__device__ __forceinline__ unsigned smem_u32(const void* p) {
    return (unsigned)__cvta_generic_to_shared(p);
}
__device__ __forceinline__ void cp4(unsigned dst, const void* src, int sz) {
    asm volatile("cp.async.ca.shared.global [%0], [%1], 4, %2;" :: "r"(dst), "l"(src), "r"(sz));
}
__device__ __forceinline__ void cp16(unsigned dst, const void* src) {
    asm volatile("cp.async.ca.shared.global [%0], [%1], 16;" :: "r"(dst), "l"(src));
}
#define CP_COMMIT() asm volatile("cp.async.commit_group;")
#define CP_WAIT0()  asm volatile("cp.async.wait_group 0;")

__device__ __forceinline__ void ldsm_x4(u32* r, unsigned a) {
    asm volatile("ldmatrix.sync.aligned.m8n8.x4.shared.b16 {%0,%1,%2,%3}, [%4];"
        : "=r"(r[0]), "=r"(r[1]), "=r"(r[2]), "=r"(r[3]) : "r"(a));
}
__device__ __forceinline__ void ldsm_x2t(u32* r, unsigned a) {
    asm volatile("ldmatrix.sync.aligned.m8n8.x2.trans.shared.b16 {%0,%1}, [%2];"
        : "=r"(r[0]), "=r"(r[1]) : "r"(a));
}
__device__ __forceinline__ void mma_bf16(float* d, const u32* a, const u32* b) {
    asm volatile("mma.sync.aligned.m16n8k16.row.col.f32.bf16.bf16.f32 "
        "{%0,%1,%2,%3}, {%4,%5,%6,%7}, {%8,%9}, {%0,%1,%2,%3};"
        : "+f"(d[0]), "+f"(d[1]), "+f"(d[2]), "+f"(d[3])
        : "r"(a[0]), "r"(a[1]), "r"(a[2]), "r"(a[3]), "r"(b[0]), "r"(b[1]));
}

// ============================================================================
// xt: x NCHW f32 -> d_xt NHWC bf16 (zero halos untouched). grid (6,192,8), 256.
// ============================================================================
__global__ void __launch_bounds__(256) xt_kernel(const float* __restrict__ x) {
    const int wc = blockIdx.x, r = blockIdx.y, b = blockIdx.z;
    const int w0 = wc * 64;
    const int tid = threadIdx.x;
    __shared__ float s[64][65];
    #pragma unroll 4
    for (int i = tid; i < 4096; i += 256) {
        int ci = i >> 6, w = i & 63;
        s[ci][w] = x[((size_t)(b * 64 + ci) * HIN + r) * WIN + w0 + w];
    }
    __syncthreads();
    const int px = tid >> 2, q = tid & 3;
    u32 pk[8];
    #pragma unroll
    for (int j = 0; j < 8; j++) {
        __nv_bfloat162 t = __floats2bfloat162_rn(s[q * 16 + 2 * j][px], s[q * 16 + 2 * j + 1][px]);
        pk[j] = *(u32*)&t;
    }
    uint4* dst = (uint4*)(d_xt + (((size_t)(b * XTROWS + r + 1) * XTPX + w0 + px + 1) * 64 + q * 16));
    dst[0] = make_uint4(pk[0], pk[1], pk[2], pk[3]);
    dst[1] = make_uint4(pk[4], pk[5], pk[6], pk[7]);
}

// ============================================================================
// Gate (unchanged)
// ============================================================================
__global__ void gate_kernel(const float* __restrict__ emb,
                            const float* __restrict__ g1w, const float* __restrict__ g1b,
                            const float* __restrict__ g2w, const float* __restrict__ g2b,
                            float* __restrict__ out) {
    const int b = blockIdx.x, gate = blockIdx.y, c = threadIdx.x;
    const float* gw = (gate == 0) ? g1w : g2w;
    const float* gb = (gate == 0) ? g1b : g2b;
    __shared__ float s_emb[EDIM];
    __shared__ float s_log[COUT];
    __shared__ float s_exp[COUT];
    s_emb[c] = emb[b * EDIM + c];
    __syncthreads();
    float l = gb[c];
    #pragma unroll 8
    for (int e = 0; e < EDIM; e++) l += s_emb[e] * gw[e * COUT + c];
    s_log[c] = l;
    __syncthreads();
    int rank = 0; float m = -1e30f;
    for (int j = 0; j < COUT; j++) {
        float lj = s_log[j];
        if (lj > l || (lj == l && j < c)) rank++;
        if (lj > m) m = lj;
    }
    bool sel = (rank < TOPK);
    float ev = sel ? expf(l - m) : 0.0f;
    s_exp[c] = ev;
    __syncthreads();
    float s = 0.f;
    for (int j = 0; j < COUT; j++) s += s_exp[j];
    float gv = ev / s;
    out[OUT6_SIZE + gate * (BATCH * COUT) + b * COUT + c] = gv;
    if (gate == 0) {
        if (sel) { d_idx1[b * TOPK + rank] = c; d_gv1[b * TOPK + rank] = gv; }
    } else {
        d_slot2[b * COUT + c] = sel ? rank : -1;
        if (sel) { d_idx2[b * TOPK + rank] = c; d_gv2[b * TOPK + rank] = gv; }
    }
}

// ============================================================================
// wpack: b<8 gather+scale conv weights; b==8 transpose dsw -> d_dswt. grid 9.
// ============================================================================
__global__ void __launch_bounds__(256) wpack_kernel(const float* __restrict__ w1,
                                                    const float* __restrict__ w2,
                                                    const float* __restrict__ dsw) {
    const int b = blockIdx.x, tid = threadIdx.x;
    if (b == 8) {
        for (int i = tid; i < CIN * COUT; i += 256) {
            int ci = i >> 7, co = i & 127;
            d_dswt[i] = dsw[co * CIN + ci];
        }
        return;
    }
    for (int i = tid; i < 32 * 576; i += 256) {
        int co = i / 576, kk = i - co * 576;
        int ci = kk / 9, tap = kk - ci * 9;
        float v = w1[((size_t)d_idx1[b * 32 + co] * 64 + ci) * 9 + tap] * d_gv1[b * 32 + co];
        d_w1p[(size_t)b * 18432 + (tap * 64 + ci) * 32 + co] = __float2bfloat16(v);
    }
    for (int i = tid; i < 32 * 288; i += 256) {
        int co = i / 288, kk = i - co * 288;
        int ci = kk / 9, tap = kk - ci * 9;
        float v = w2[((size_t)d_idx2[b * 32 + co] * 128 + d_idx1[b * 32 + ci]) * 9 + tap] * d_gv2[b * 32 + co];
        d_w2p[(size_t)b * 9216 + (tap * 32 + ci) * 32 + co] = __float2bfloat16(v);
    }
}

// ============================================================================
// ds (R12/R13 version): weights from pre-transposed d_dswt.
// ============================================================================
#define DS_SMEM ((8192 + 8192 + 384) * 4)
__global__ void __launch_bounds__(256, 2) ds_kernel(const float* __restrict__ x,
                                                    const float* __restrict__ gamma,
                                                    const float* __restrict__ beta,
                                                    float* __restrict__ out) {
    extern __shared__ __align__(16) float dsm[];
    float* s_xc    = dsm;
    float* s_wt    = dsm + 8192;
    float* s_scale = dsm + 16384;
    float* s_betav = s_scale + 128;
    int*   s_slot  = (int*)(s_betav + 128);

    const int b  = blockIdx.y;
    const int h0 = (blockIdx.x / 12) * 8;
    const int w0 = (blockIdx.x % 12) * 16;
    const int tid = threadIdx.x;
    const int po  = tid >> 4;
    const int cg  = tid & 15;

    const float* xb = x + (size_t)b * CIN * HIN * WIN;
    #pragma unroll 8
    for (int k = 0; k < 32; k++) {
        int i = tid + k * 256;
        int ci = i >> 7, p = i & 127, r = (p >> 4), j = p & 15;
        cp4(smem_u32(&s_xc[i]), xb + (size_t)ci * HIN * WIN + (2 * (h0 + r)) * WIN + 2 * (w0 + j), 4);
    }
    #pragma unroll
    for (int k = 0; k < 8; k++) {
        int i = tid + k * 256;
        cp16(smem_u32(&s_wt[i * 4]), d_dswt + i * 4);
    }
    if (tid < 128) {
        s_scale[tid] = gamma[tid] * rsqrtf(1.0f + 1e-5f);
        s_betav[tid] = beta[tid];
        s_slot[tid]  = d_slot2[b * COUT + tid];
    }
    CP_COMMIT(); CP_WAIT0();
    __syncthreads();

    u64 acc[8][4];
    #pragma unroll
    for (int c = 0; c < 8; c++)
        #pragma unroll
        for (int m = 0; m < 4; m++) acc[c][m] = 0ull;

    #pragma unroll 4
    for (int ci = 0; ci < 64; ci++) {
        const ulonglong2* xq = (const ulonglong2*)&s_xc[ci * 128 + 8 * po];
        ulonglong2 X0 = xq[0], X1 = xq[1];
        const float4* wq = (const float4*)&s_wt[ci * 128 + 8 * cg];
        float4 wa = wq[0], wb2 = wq[1];
        u64 W[8];
        W[0] = pk2(wa.x, wa.x);   W[1] = pk2(wa.y, wa.y);
        W[2] = pk2(wa.z, wa.z);   W[3] = pk2(wa.w, wa.w);
        W[4] = pk2(wb2.x, wb2.x); W[5] = pk2(wb2.y, wb2.y);
        W[6] = pk2(wb2.z, wb2.z); W[7] = pk2(wb2.w, wb2.w);
        #pragma unroll
        for (int c = 0; c < 8; c++) {
            fma2(acc[c][0], X0.x, W[c]);
            fma2(acc[c][1], X0.y, W[c]);
            fma2(acc[c][2], X1.x, W[c]);
            fma2(acc[c][3], X1.y, W[c]);
        }
    }

    const int hr  = h0 + (po >> 1);
    const int wc0 = w0 + (po & 1) * 8;
    #pragma unroll
    for (int c = 0; c < 8; c++) {
        int co = 8 * cg + c;
        float v[8];
        #pragma unroll
        for (int m = 0; m < 4; m++) upk2(acc[c][m], v[2 * m], v[2 * m + 1]);
        float sc = s_scale[co], be = s_betav[co];
        #pragma unroll
        for (int k = 0; k < 8; k++) v[k] = v[k] * sc + be;
        if (s_slot[co] < 0) {
            #pragma unroll
            for (int k = 0; k < 8; k++) v[k] = leaky(v[k]);
        }
        float* base = &out[((size_t)(b * COUT + co) * OH + hr) * OW + wc0];
        *(float4*)base       = make_float4(v[0], v[1], v[2], v[3]);
        *(float4*)(base + 4) = make_float4(v[4], v[5], v[6], v[7]);
    }
}

// ============================================================================
// conv1_tc (R11/R13 version — 1 row per block): grid (2, 96, BATCH), 192 thr.
// ============================================================================
#define C1_ROWB (XTPX * 128)
#define C1_SMEM (3 * 193 * 128 + 18432 * 2)
__global__ void __launch_bounds__(192, 2) conv1_tc() {
    extern __shared__ __align__(16) char sm1[];
    char* sx = sm1;
    char* sw = sm1 + 3 * 193 * 128;
    float* sep = (float*)sm1;

    const int half = blockIdx.x, h = blockIdx.y, b = blockIdx.z;
    const int w0 = half * 96;
    const int tid = threadIdx.x, wid = tid >> 5, lane = tid & 31;

    {
        const char* xb = (const char*)(d_xt + (((size_t)(b * XTROWS + 2 * h) * XTPX + 2 * w0) * 64));
        for (int i = tid; i < 3 * 1544; i += 192) {
            int r = i / 1544, off = (i - r * 1544) * 16;
            cp16(smem_u32(sx + r * (193 * 128) + off), xb + (size_t)r * C1_ROWB + off);
        }
        const char* wb = (const char*)(d_w1p + (size_t)b * 18432);
        for (int i = tid; i < 2304; i += 192)
            cp16(smem_u32(sw + i * 16), wb + i * 16);
        CP_COMMIT(); CP_WAIT0();
    }
    __syncthreads();

    float acc[4][4];
    #pragma unroll
    for (int n = 0; n < 4; n++)
        #pragma unroll
        for (int k = 0; k < 4; k++) acc[n][k] = 0.f;

    const int moff = lane & 15;
    const int kbyte = (lane < 16) ? 0 : 16;
    const int mpx = wid * 16 + moff;
    const unsigned sxb = smem_u32(sx);
    const unsigned swb = smem_u32(sw);
    const int brow0 = (lane & 15) * 64;

    #pragma unroll 4
    for (int kc = 0; kc < 36; kc++) {
        const int tap = kc >> 2, cc = kc & 3;
        const int dh = tap / 3, dw = tap - 3 * dh;
        u32 a[4];
        ldsm_x4(a, sxb + dh * (193 * 128) + (2 * mpx + dw) * 128 + cc * 32 + kbyte);
        const unsigned bbase = swb + kc * 16 * 64 + brow0;
        #pragma unroll
        for (int n = 0; n < 4; n++) {
            u32 bb[2];
            ldsm_x2t(bb, bbase + n * 16);
            mma_bf16(acc[n], a, bb);
        }
    }
    __syncthreads();

    const int gid = lane >> 2, tig = lane & 3;
    #pragma unroll
    for (int n = 0; n < 4; n++) {
        int co = n * 8 + 2 * tig;
        int p0 = wid * 16 + gid;
        sep[p0 * 33 + co]           = acc[n][0];
        sep[p0 * 33 + co + 1]       = acc[n][1];
        sep[(p0 + 8) * 33 + co]     = acc[n][2];
        sep[(p0 + 8) * 33 + co + 1] = acc[n][3];
    }
    __syncthreads();

    const int px = tid >> 1, hc = tid & 1;
    u32 pk[8];
    #pragma unroll
    for (int j = 0; j < 8; j++) {
        float v0 = leaky(sep[px * 33 + hc * 16 + 2 * j]);
        float v1 = leaky(sep[px * 33 + hc * 16 + 2 * j + 1]);
        __nv_bfloat162 t = __floats2bfloat162_rn(v0, v1);
        pk[j] = *(u32*)&t;
    }
    uint4* dst = (uint4*)(d_o2 + (((size_t)(b * O2R + h + 1) * O2PX + 1 + w0 + px) * 32 + hc * 16));
    dst[0] = make_uint4(pk[0], pk[1], pk[2], pk[3]);
    dst[1] = make_uint4(pk[4], pk[5], pk[6], pk[7]);
}

// ============================================================================
// conv2_tc (R11/R13 version — 1 row per block): grid (96, BATCH), 192 thr.
// ============================================================================
#define C2_ROWB (O2PX * 64)
#define C2_SMEM (3 * C2_ROWB + 9216 * 2)
__global__ void __launch_bounds__(192, 3) conv2_tc(float* __restrict__ out) {
    extern __shared__ __align__(16) char sm2[];
    char* sx = sm2;
    char* sw = sm2 + 3 * C2_ROWB;
    float* sep = (float*)sm2;
    __shared__ int s_idx2s[32];

    const int h = blockIdx.x, b = blockIdx.y;
    const int tid = threadIdx.x, wid = tid >> 5, lane = tid & 31;

    {
        const char* xb = (const char*)(d_o2 + ((size_t)(b * O2R + h) * O2PX) * 32);
        for (int i = tid; i < 3 * 776; i += 192) {
            int r = i / 776, off = (i - r * 776) * 16;
            cp16(smem_u32(sx + r * C2_ROWB + off), xb + (size_t)r * C2_ROWB + off);
        }
        const char* wb = (const char*)(d_w2p + (size_t)b * 9216);
        for (int i = tid; i < 1152; i += 192)
            cp16(smem_u32(sw + i * 16), wb + i * 16);
        if (tid < 32) s_idx2s[tid] = d_idx2[b * 32 + tid];
        CP_COMMIT(); CP_WAIT0();
    }
    __syncthreads();

    float acc[2][4][4];
    #pragma unroll
    for (int mi = 0; mi < 2; mi++)
        #pragma unroll
        for (int n = 0; n < 4; n++)
            #pragma unroll
            for (int k = 0; k < 4; k++) acc[mi][n][k] = 0.f;

    const int moff = lane & 15;
    const int kbyte = (lane < 16) ? 0 : 16;
    const unsigned sxb = smem_u32(sx);
    const unsigned swb = smem_u32(sw);
    const int brow0 = (lane & 15) * 64;

    #pragma unroll 3
    for (int kc = 0; kc < 18; kc++) {
        const int tap = kc >> 1, cc = kc & 1;
        const int dh = tap / 3, dw = tap - 3 * dh;
        u32 bb[4][2];
        const unsigned bbase = swb + kc * 16 * 64 + brow0;
        #pragma unroll
        for (int n = 0; n < 4; n++) ldsm_x2t(bb[n], bbase + n * 16);
        #pragma unroll
        for (int mi = 0; mi < 2; mi++) {
            u32 a[4];
            const int p = (2 * wid + mi) * 16 + moff + dw;
            ldsm_x4(a, sxb + dh * C2_ROWB + p * 64 + cc * 32 + kbyte);
            #pragma unroll
            for (int n = 0; n < 4; n++) mma_bf16(acc[mi][n], a, bb[n]);
        }
    }
    __syncthreads();

    const int gid = lane >> 2, tig = lane & 3;
    #pragma unroll
    for (int mi = 0; mi < 2; mi++) {
        int p0 = (2 * wid + mi) * 16 + gid;
        #pragma unroll
        for (int n = 0; n < 4; n++) {
            int co = n * 8 + 2 * tig;
            sep[p0 * 33 + co]           = acc[mi][n][0];
            sep[p0 * 33 + co + 1]       = acc[mi][n][1];
            sep[(p0 + 8) * 33 + co]     = acc[mi][n][2];
            sep[(p0 + 8) * 33 + co + 1] = acc[mi][n][3];
        }
    }
    __syncthreads();

    for (int co = 0; co < 32; co++) {
        float v = sep[tid * 33 + co];
        float* op = &out[((size_t)(b * COUT + s_idx2s[co]) * OH + h) * OW + tid];
        *op = leaky(leaky(v) + *op);
    }
}

// ============================================================================
// Launch: fork/join overlap. FIXED vs R15: ds now waits on wpack (evWp) —
// it reads d_dswt which wpack writes. All other edges unchanged.
// ============================================================================
extern "C" void kernel_launch(void* const* d_in, const int* in_sizes, int n_in,
                              void* d_out, int out_size) {
    const float* x     = (const float*)d_in[0];
    const float* emb   = (const float*)d_in[1];
    const float* w1    = (const float*)d_in[2];
    const float* w2    = (const float*)d_in[3];
    const float* dsw   = (const float*)d_in[4];
    const float* gam   = (const float*)d_in[5];
    const float* bet   = (const float*)d_in[6];
    const float* g1w   = (const float*)d_in[7];
    const float* g1b   = (const float*)d_in[8];
    const float* g2w   = (const float*)d_in[9];
    const float* g2b   = (const float*)d_in[10];
    float* out = (float*)d_out;

    static cudaStream_t s2 = nullptr;
    static cudaEvent_t evFork = nullptr, evWp = nullptr, evXt = nullptr, evDs = nullptr;
    if (s2 == nullptr) {
        cudaStreamCreateWithFlags(&s2, cudaStreamNonBlocking);
        cudaEventCreateWithFlags(&evFork, cudaEventDisableTiming);
        cudaEventCreateWithFlags(&evWp,   cudaEventDisableTiming);
        cudaEventCreateWithFlags(&evXt,   cudaEventDisableTiming);
        cudaEventCreateWithFlags(&evDs,   cudaEventDisableTiming);
        cudaFuncSetAttribute(ds_kernel, cudaFuncAttributeMaxDynamicSharedMemorySize, DS_SMEM);
        cudaFuncSetAttribute(conv1_tc,  cudaFuncAttributeMaxDynamicSharedMemorySize, C1_SMEM);
        cudaFuncSetAttribute(conv2_tc,  cudaFuncAttributeMaxDynamicSharedMemorySize, C2_SMEM);
    }

    // Fork side stream from origin stream (required for stream capture).
    cudaEventRecord(evFork, 0);
    cudaStreamWaitEvent(s2, evFork, 0);

    // side stream: xt (independent of gate/wpack)
    xt_kernel<<<dim3(6, 192, BATCH), 256, 0, s2>>>(x);
    cudaEventRecord(evXt, s2);

    // main stream: gate -> wpack (wpack writes d_w1p, d_w2p, d_dswt)
    gate_kernel<<<dim3(BATCH, 2), 128>>>(emb, g1w, g1b, g2w, g2b, out);
    wpack_kernel<<<9, 256>>>(w1, w2, dsw);
    cudaEventRecord(evWp, 0);

    // side stream: ds (needs gate's d_slot2 AND wpack's d_dswt — evWp covers both)
    cudaStreamWaitEvent(s2, evWp, 0);
    ds_kernel<<<dim3(144, BATCH), 256, DS_SMEM, s2>>>(x, gam, bet, out);
    cudaEventRecord(evDs, s2);

    // main stream: conv1 (needs xt + wpack), conv2 (needs conv1 + ds)
    cudaStreamWaitEvent(0, evXt, 0);
    conv1_tc<<<dim3(2, OH, BATCH), 192, C1_SMEM>>>();
    cudaStreamWaitEvent(0, evDs, 0);
    conv2_tc<<<dim3(OH, BATCH), 192, C2_SMEM>>>(out);
}